// round 10
// baseline (speedup 1.0000x reference)
#include <cuda_runtime.h>
#include <cuda_fp16.h>
#include <cstdint>

#define MAX_N 50000
#define MAX_E 800000
#define D 128
#define SCAN_B 512
#define MAX_BLK 128   // >= ceil(MAX_N/SCAN_B)

// Scratch (device globals: allocation forbidden in kernel_launch)
__device__ int    g_mode;             // 1 = edge_index is int64, 0 = int32
__device__ int    g_deg[MAX_N];       // edge in-degree (excl self-loop)
__device__ int    g_off[MAX_N];       // CSR row offsets
__device__ int    g_cur[MAX_N];       // fill cursors
__device__ int    g_bsum[MAX_BLK];    // scan block sums
__device__ float  g_dis[MAX_N];       // rsqrt(deg+1)
__device__ int    g_src[MAX_E];       // CSR column indices (source nodes)
__device__ __half g_h[4ull * MAX_N * D];  // h = x @ W^T in fp16, per set

// ---------------------------------------------------------------------------
__global__ void k_detect(const void* ei, int E, int N) {
    if (threadIdx.x == 0 && blockIdx.x == 0) {
        const long long* p64 = (const long long*)ei;
        int n = E < 32 ? E : 32;
        int ok64 = 1;
        for (int i = 0; i < n; i++) {
            long long v = p64[i];
            if (v < 0 || v >= (long long)N) { ok64 = 0; break; }
        }
        g_mode = ok64;
    }
}

__device__ __forceinline__ int edge_at(const void* ei, long long idx, int mode) {
    if (mode) return (int)((const long long*)ei)[idx];
    return ((const int*)ei)[idx];
}

__global__ void k_zero(int N) {
    int i = blockIdx.x * blockDim.x + threadIdx.x;
    if (i < N) g_deg[i] = 0;
}

__global__ void k_count(const void* __restrict__ ei, int E, int N) {
    int e = blockIdx.x * blockDim.x + threadIdx.x;
    if (e >= E) return;
    int mode = g_mode;
    int d = edge_at(ei, (long long)E + e, mode);
    if (d >= 0 && d < N) atomicAdd(&g_deg[d], 1);
}

__global__ void k_scan_block(int N) {
    __shared__ int sm[SCAN_B];
    int i = blockIdx.x * SCAN_B + threadIdx.x;
    int v = (i < N) ? g_deg[i] : 0;
    sm[threadIdx.x] = v;
    __syncthreads();
#pragma unroll
    for (int o = 1; o < SCAN_B; o <<= 1) {
        int t = (threadIdx.x >= o) ? sm[threadIdx.x - o] : 0;
        __syncthreads();
        sm[threadIdx.x] += t;
        __syncthreads();
    }
    if (i < N) g_off[i] = sm[threadIdx.x] - v;   // exclusive
    if (threadIdx.x == SCAN_B - 1) g_bsum[blockIdx.x] = sm[SCAN_B - 1];
}

__global__ void k_scan_sums(int nb) {
    if (threadIdx.x == 0) {
        int acc = 0;
        for (int b = 0; b < nb; b++) { int t = g_bsum[b]; g_bsum[b] = acc; acc += t; }
    }
}

__global__ void k_finalize(int N) {
    int i = blockIdx.x * blockDim.x + threadIdx.x;
    if (i < N) {
        int o = g_off[i] + g_bsum[i / SCAN_B];
        g_off[i] = o;
        g_cur[i] = o;
        g_dis[i] = rsqrtf((float)(g_deg[i] + 1));
    }
}

__global__ void k_fill(const void* __restrict__ ei, int E, int N) {
    int e = blockIdx.x * blockDim.x + threadIdx.x;
    if (e >= E) return;
    int mode = g_mode;
    int s = edge_at(ei, e, mode);
    int d = edge_at(ei, (long long)E + e, mode);
    if (s >= 0 && s < N && d >= 0 && d < N) {
        int pos = atomicAdd(&g_cur[d], 1);
        if (pos >= 0 && pos < E) g_src[pos] = s;
    }
}

// ---------------------------------------------------------------------------
// GEMM (no bias): g_h[set] = fp16( x_set @ W^T )   (fp16 HMMA m16n8k16, f32 acc)
// Block 128(M)x128(N), 8 warps as 2(M)x4(N), warp 64x32.
// Full W AND full x tile staged fp16 in dynamic smem; ONE sync; 8 K-steps.
#define SP 68   // smem pitch in half2 units: (4g+c)%32 distinct -> conflict-free

__device__ __forceinline__ uint32_t pack_h2(float lo, float hi) {
    __half2 h = __floats2half2_rn(lo, hi);
    return *(uint32_t*)&h;
}

__device__ __forceinline__ void mma_f16(float* d, const uint32_t* a, const uint32_t* b) {
    asm volatile(
        "mma.sync.aligned.m16n8k16.row.col.f32.f16.f16.f32 "
        "{%0,%1,%2,%3}, {%4,%5,%6,%7}, {%8,%9}, {%0,%1,%2,%3};"
        : "+f"(d[0]), "+f"(d[1]), "+f"(d[2]), "+f"(d[3])
        : "r"(a[0]), "r"(a[1]), "r"(a[2]), "r"(a[3]), "r"(b[0]), "r"(b[1]));
}

__global__ void __launch_bounds__(256) k_gemm(
        const float* __restrict__ x0, const float* __restrict__ x1,
        const float* __restrict__ x2, const float* __restrict__ x3,
        const float* __restrict__ W1, const float* __restrict__ W2,
        int N) {
    extern __shared__ uint32_t smem[];
    uint32_t (*Wh)[SP] = (uint32_t(*)[SP])smem;               // W[n][k] half2
    uint32_t (*Xh)[SP] = (uint32_t(*)[SP])(smem + 128 * SP);  // x[m][k] half2

    int set = blockIdx.y;
    const float* xp = (set == 0) ? x0 : (set == 1) ? x1 : (set == 2) ? x2 : x3;
    const float* Wp = (set == 0 || set == 2) ? W1 : W2;
    __half* h = g_h + (size_t)set * N * D;

    int tid = threadIdx.x;
    int m0 = blockIdx.x * 128;
    int warp = tid >> 5, lane = tid & 31;
    int wm = warp >> 2, wn = warp & 3;        // 2 x 4 warp grid
    int g = lane >> 2, c = lane & 3;

    // stage full W + full x tile (16 float4 each per thread), max MLP
    {
        int row = tid >> 1;                // 2 threads per row
        int qb = (tid & 1) * 16;           // 16 float4 per thread per tensor
        const float4* wsrc = (const float4*)&Wp[row * D] + qb;
        int gm = m0 + row;
        const float4* xsrc = (gm < N) ? (const float4*)&xp[(size_t)gm * D] + qb : nullptr;

        float4 wv[16], xv[16];
#pragma unroll
        for (int r = 0; r < 16; r++) wv[r] = wsrc[r];
#pragma unroll
        for (int r = 0; r < 16; r++)
            xv[r] = xsrc ? xsrc[r] : make_float4(0.f, 0.f, 0.f, 0.f);

#pragma unroll
        for (int r = 0; r < 16; r++) {
            int q4 = qb + r;
            Wh[row][q4 * 2]     = pack_h2(wv[r].x, wv[r].y);
            Wh[row][q4 * 2 + 1] = pack_h2(wv[r].z, wv[r].w);
        }
#pragma unroll
        for (int r = 0; r < 16; r++) {
            int q4 = qb + r;
            Xh[row][q4 * 2]     = pack_h2(xv[r].x, xv[r].y);
            Xh[row][q4 * 2 + 1] = pack_h2(xv[r].z, xv[r].w);
        }
    }
    __syncthreads();

    float acc[4][4][4];
#pragma unroll
    for (int mi = 0; mi < 4; mi++)
#pragma unroll
        for (int ni = 0; ni < 4; ni++)
#pragma unroll
            for (int r = 0; r < 4; r++) acc[mi][ni][r] = 0.0f;

#pragma unroll
    for (int ks = 0; ks < 8; ks++) {
        int kk = ks * 8;
        uint32_t a[4][4], b[4][2];
#pragma unroll
        for (int mi = 0; mi < 4; mi++) {
            int r = wm * 64 + mi * 16 + g;
            a[mi][0] = Xh[r][kk + c];
            a[mi][1] = Xh[r + 8][kk + c];
            a[mi][2] = Xh[r][kk + c + 4];
            a[mi][3] = Xh[r + 8][kk + c + 4];
        }
#pragma unroll
        for (int ni = 0; ni < 4; ni++) {
            int n = wn * 32 + ni * 8 + g;
            b[ni][0] = Wh[n][kk + c];
            b[ni][1] = Wh[n][kk + c + 4];
        }
#pragma unroll
        for (int mi = 0; mi < 4; mi++)
#pragma unroll
            for (int ni = 0; ni < 4; ni++)
                mma_f16(acc[mi][ni], a[mi], b[ni]);
    }

    // epilogue: convert to fp16, write half2 per fragment pair
#pragma unroll
    for (int ni = 0; ni < 4; ni++) {
        int cb = wn * 32 + ni * 8 + 2 * c;
#pragma unroll
        for (int mi = 0; mi < 4; mi++) {
            int r0 = m0 + wm * 64 + mi * 16 + g;
            int r1 = r0 + 8;
            if (r0 < N)
                *(__half2*)&h[(size_t)r0 * D + cb] =
                    __floats2half2_rn(acc[mi][ni][0], acc[mi][ni][1]);
            if (r1 < N)
                *(__half2*)&h[(size_t)r1 * D + cb] =
                    __floats2half2_rn(acc[mi][ni][2], acc[mi][ni][3]);
        }
    }
}

// ---------------------------------------------------------------------------
// Aggregation: out_s[i] = sum_j norm_ij * h_s[j]  + b_s   (fp32 accumulate)
// One warp per node. Lanes 0-15 handle sets {0,1}, lanes 16-31 sets {2,3}.
__global__ void k_agg(const float* __restrict__ b1, const float* __restrict__ b2,
                      float* __restrict__ out, int N) {
    int gt = blockIdx.x * blockDim.x + threadIdx.x;
    int i = gt >> 5;
    int lane = gt & 31;
    if (i >= N) return;

    int pair = lane >> 4;        // 0 -> sets 0,1 ; 1 -> sets 2,3
    int cp = lane & 15;          // uint4 column index (8 halves)
    int setA = pair * 2;         // 0 or 2  (bias b1)
    int setB = setA + 1;         // 1 or 3  (bias b2)

    const uint4* HA = (const uint4*)(g_h + (size_t)setA * N * D);
    const uint4* HB = (const uint4*)(g_h + (size_t)setB * N * D);

    float di = g_dis[i];
    float d2 = di * di;

    float accA[8], accB[8];
    {   // self-loop term
        uint4 ua = HA[(size_t)i * 16 + cp];
        uint4 ub = HB[(size_t)i * 16 + cp];
        const half2* pa = (const half2*)&ua;
        const half2* pb = (const half2*)&ub;
#pragma unroll
        for (int q = 0; q < 4; q++) {
            float2 fa = __half22float2(pa[q]);
            float2 fb = __half22float2(pb[q]);
            accA[2 * q] = fa.x * d2; accA[2 * q + 1] = fa.y * d2;
            accB[2 * q] = fb.x * d2; accB[2 * q + 1] = fb.y * d2;
        }
    }

    int beg = g_off[i];
    int end = beg + g_deg[i];
    for (int j = beg; j < end; j++) {
        int s = g_src[j];
        float w = di * g_dis[s];
        uint4 ua = HA[(size_t)s * 16 + cp];
        uint4 ub = HB[(size_t)s * 16 + cp];
        const half2* pa = (const half2*)&ua;
        const half2* pb = (const half2*)&ub;
#pragma unroll
        for (int q = 0; q < 4; q++) {
            float2 fa = __half22float2(pa[q]);
            float2 fb = __half22float2(pb[q]);
            accA[2 * q]     = fmaf(fa.x, w, accA[2 * q]);
            accA[2 * q + 1] = fmaf(fa.y, w, accA[2 * q + 1]);
            accB[2 * q]     = fmaf(fb.x, w, accB[2 * q]);
            accB[2 * q + 1] = fmaf(fb.y, w, accB[2 * q + 1]);
        }
    }

    // bias + write
    int col = cp * 8;
    float4 bA0 = *(const float4*)&b1[col];
    float4 bA1 = *(const float4*)&b1[col + 4];
    float4 bB0 = *(const float4*)&b2[col];
    float4 bB1 = *(const float4*)&b2[col + 4];

    float* oA = out + (size_t)setA * N * D + (size_t)i * D + col;
    float* oB = out + (size_t)setB * N * D + (size_t)i * D + col;
    *(float4*)oA       = make_float4(accA[0] + bA0.x, accA[1] + bA0.y,
                                     accA[2] + bA0.z, accA[3] + bA0.w);
    *(float4*)(oA + 4) = make_float4(accA[4] + bA1.x, accA[5] + bA1.y,
                                     accA[6] + bA1.z, accA[7] + bA1.w);
    *(float4*)oB       = make_float4(accB[0] + bB0.x, accB[1] + bB0.y,
                                     accB[2] + bB0.z, accB[3] + bB0.w);
    *(float4*)(oB + 4) = make_float4(accB[4] + bB1.x, accB[5] + bB1.y,
                                     accB[6] + bB1.z, accB[7] + bB1.w);
}

// ---------------------------------------------------------------------------
extern "C" void kernel_launch(void* const* d_in, const int* in_sizes, int n_in,
                              void* d_out, int out_size) {
    const float* x0 = (const float*)d_in[0];  // x_r1 (W1,b1)
    const float* x1 = (const float*)d_in[1];  // x_r2 (W2,b2)
    const float* x2 = (const float*)d_in[2];  // x_i1 (W1,b1)
    const float* x3 = (const float*)d_in[3];  // x_i2 (W2,b2)
    const void*  ei = d_in[4];                // edge_index: int64 OR int32
    const float* W1 = (const float*)d_in[5];
    const float* b1 = (const float*)d_in[6];
    const float* W2 = (const float*)d_in[7];
    const float* b2 = (const float*)d_in[8];
    float* out = (float*)d_out;

    int N = in_sizes[0] / D;
    int E = in_sizes[4] / 2;
    int nb_scan = (N + SCAN_B - 1) / SCAN_B;

    // dtype probe + CSR build + normalization
    k_detect<<<1, 32>>>(ei, E, N);
    k_zero<<<(N + 255) / 256, 256>>>(N);
    k_count<<<(E + 255) / 256, 256>>>(ei, E, N);

    // GEMM first (independent of CSR): h = fp16(x @ W^T), no bias
    {
        int smem = 2 * 128 * SP * sizeof(uint32_t);  // 69632 B
        cudaFuncSetAttribute(k_gemm, cudaFuncAttributeMaxDynamicSharedMemorySize, smem);
        dim3 grid((N + 127) / 128, 4);
        k_gemm<<<grid, 256, smem>>>(x0, x1, x2, x3, W1, W2, N);
    }

    k_scan_block<<<nb_scan, SCAN_B>>>(N);
    k_scan_sums<<<1, 32>>>(nb_scan);
    k_finalize<<<(N + 255) / 256, 256>>>(N);
    k_fill<<<(E + 255) / 256, 256>>>(ei, E, N);

    // aggregate fp16 h with fp32 accumulation, add bias, write out
    {
        long long threads = (long long)N * 32;
        int blocks = (int)((threads + 255) / 256);
        k_agg<<<blocks, 256>>>(b1, b2, out, N);
    }
}

// round 11
// speedup vs baseline: 1.1181x; 1.1181x over previous
#include <cuda_runtime.h>
#include <cuda_fp16.h>
#include <cstdint>

#define MAX_N 50000
#define MAX_E 800000
#define D 128
#define SCAN_B 512
#define MAX_BLK 128   // >= ceil(MAX_N/SCAN_B)

// Scratch (device globals: allocation forbidden in kernel_launch)
__device__ int    g_mode;             // 1 = edge_index is int64, 0 = int32
__device__ int    g_deg[MAX_N];       // edge in-degree (excl self-loop)
__device__ int    g_off[MAX_N];       // CSR row offsets
__device__ int    g_cur[MAX_N];       // fill cursors
__device__ int    g_bsum[MAX_BLK];    // scan block sums
__device__ float  g_dis[MAX_N];       // rsqrt(deg+1)
__device__ int    g_src[MAX_E];       // CSR column indices (source nodes)
__device__ __half g_h[4ull * MAX_N * D];  // h = x @ W^T in fp16, per set

// ---------------------------------------------------------------------------
// fused: zero degree array + dtype probe (thread 0 of block 0)
__global__ void k_detect_zero(const void* ei, int E, int N) {
    int i = blockIdx.x * blockDim.x + threadIdx.x;
    if (i < N) g_deg[i] = 0;
    if (i == 0) {
        const long long* p64 = (const long long*)ei;
        int n = E < 32 ? E : 32;
        int ok64 = 1;
        for (int k = 0; k < n; k++) {
            long long v = p64[k];
            if (v < 0 || v >= (long long)N) { ok64 = 0; break; }
        }
        g_mode = ok64;
    }
}

__device__ __forceinline__ int edge_at(const void* ei, long long idx, int mode) {
    if (mode) return (int)((const long long*)ei)[idx];
    return ((const int*)ei)[idx];
}

__global__ void k_count(const void* __restrict__ ei, int E, int N) {
    int e = blockIdx.x * blockDim.x + threadIdx.x;
    if (e >= E) return;
    int mode = g_mode;
    int d = edge_at(ei, (long long)E + e, mode);
    if (d >= 0 && d < N) atomicAdd(&g_deg[d], 1);
}

__global__ void k_scan_block(int N) {
    __shared__ int sm[SCAN_B];
    int i = blockIdx.x * SCAN_B + threadIdx.x;
    int v = (i < N) ? g_deg[i] : 0;
    sm[threadIdx.x] = v;
    __syncthreads();
#pragma unroll
    for (int o = 1; o < SCAN_B; o <<= 1) {
        int t = (threadIdx.x >= o) ? sm[threadIdx.x - o] : 0;
        __syncthreads();
        sm[threadIdx.x] += t;
        __syncthreads();
    }
    if (i < N) g_off[i] = sm[threadIdx.x] - v;   // exclusive
    if (threadIdx.x == SCAN_B - 1) g_bsum[blockIdx.x] = sm[SCAN_B - 1];
}

__global__ void k_scan_sums(int nb) {
    if (threadIdx.x == 0) {
        int acc = 0;
        for (int b = 0; b < nb; b++) { int t = g_bsum[b]; g_bsum[b] = acc; acc += t; }
    }
}

__global__ void k_finalize(int N) {
    int i = blockIdx.x * blockDim.x + threadIdx.x;
    if (i < N) {
        int o = g_off[i] + g_bsum[i / SCAN_B];
        g_off[i] = o;
        g_cur[i] = o;
        g_dis[i] = rsqrtf((float)(g_deg[i] + 1));
    }
}

__global__ void k_fill(const void* __restrict__ ei, int E, int N) {
    int e = blockIdx.x * blockDim.x + threadIdx.x;
    if (e >= E) return;
    int mode = g_mode;
    int s = edge_at(ei, e, mode);
    int d = edge_at(ei, (long long)E + e, mode);
    if (s >= 0 && s < N && d >= 0 && d < N) {
        int pos = atomicAdd(&g_cur[d], 1);
        if (pos >= 0 && pos < E) g_src[pos] = s;
    }
}

// ---------------------------------------------------------------------------
// GEMM (no bias): g_h[set] = fp16( x_set @ W^T )   (fp16 HMMA m16n8k16, f32 acc)
// Block 128(M)x128(N), 8 warps as 2(M)x4(N), warp 64x32.
// W staged once (full K, fp16). x streamed in K=32 chunks, double-buffered,
// 4 syncs total. __launch_bounds__(256,2) guarantees 2 CTAs/SM.
#define GP 68   // W pitch (half2 units): (4g+c)%32 distinct -> conflict-free
#define XP 20   // x chunk pitch (half2 units): (20g+c)%32 distinct -> conflict-free
#define NCHUNK 4  // 128 / 32

__device__ __forceinline__ uint32_t pack_h2(float lo, float hi) {
    __half2 h = __floats2half2_rn(lo, hi);
    return *(uint32_t*)&h;
}

__device__ __forceinline__ void mma_f16(float* d, const uint32_t* a, const uint32_t* b) {
    asm volatile(
        "mma.sync.aligned.m16n8k16.row.col.f32.f16.f16.f32 "
        "{%0,%1,%2,%3}, {%4,%5,%6,%7}, {%8,%9}, {%0,%1,%2,%3};"
        : "+f"(d[0]), "+f"(d[1]), "+f"(d[2]), "+f"(d[3])
        : "r"(a[0]), "r"(a[1]), "r"(a[2]), "r"(a[3]), "r"(b[0]), "r"(b[1]));
}

__global__ void __launch_bounds__(256, 2) k_gemm(
        const float* __restrict__ x0, const float* __restrict__ x1,
        const float* __restrict__ x2, const float* __restrict__ x3,
        const float* __restrict__ W1, const float* __restrict__ W2,
        int N) {
    __shared__ uint32_t Wh[128][GP];      // W[n][k] half2, full K
    __shared__ uint32_t Xh[2][128][XP];   // x chunk [m][k2], double buffer

    int set = blockIdx.y;
    const float* xp = (set == 0) ? x0 : (set == 1) ? x1 : (set == 2) ? x2 : x3;
    const float* Wp = (set == 0 || set == 2) ? W1 : W2;
    __half* h = g_h + (size_t)set * N * D;

    int tid = threadIdx.x;
    int m0 = blockIdx.x * 128;
    int warp = tid >> 5, lane = tid & 31;
    int wm = warp >> 2, wn = warp & 3;        // 2 x 4 warp grid
    int g = lane >> 2, c = lane & 3;

    // stage full W once: 128 rows x 32 float4
    for (int idx = tid; idx < 128 * 32; idx += 256) {
        int n = idx >> 5, q4 = idx & 31;
        float4 v = *(const float4*)&Wp[n * D + q4 * 4];
        Wh[n][q4 * 2]     = pack_h2(v.x, v.y);
        Wh[n][q4 * 2 + 1] = pack_h2(v.z, v.w);
    }

    // stage x chunk 0 (K=32): 128 rows x 8 float4 -> 4 float4/thread
    int sm_ = tid >> 1;                 // row (2 threads per row)
    int qb = (tid & 1) * 4;             // first of 4 float4 slots (of 8)
    int gm = m0 + sm_;
    {
        float4 p[4];
#pragma unroll
        for (int r = 0; r < 4; r++) {
            p[r] = make_float4(0.f, 0.f, 0.f, 0.f);
            if (gm < N) p[r] = *(const float4*)&xp[(size_t)gm * D + (qb + r) * 4];
        }
#pragma unroll
        for (int r = 0; r < 4; r++) {
            Xh[0][sm_][(qb + r) * 2]     = pack_h2(p[r].x, p[r].y);
            Xh[0][sm_][(qb + r) * 2 + 1] = pack_h2(p[r].z, p[r].w);
        }
    }
    __syncthreads();

    float acc[4][4][4];
#pragma unroll
    for (int mi = 0; mi < 4; mi++)
#pragma unroll
        for (int ni = 0; ni < 4; ni++)
#pragma unroll
            for (int r = 0; r < 4; r++) acc[mi][ni][r] = 0.0f;

    for (int ck = 0; ck < NCHUNK; ck++) {
        int cur = ck & 1;
        // prefetch next chunk into registers (4 consecutive LDG.128)
        float4 p[4];
        if (ck + 1 < NCHUNK) {
            int k0 = (ck + 1) * 32;
#pragma unroll
            for (int r = 0; r < 4; r++) {
                p[r] = make_float4(0.f, 0.f, 0.f, 0.f);
                if (gm < N) p[r] = *(const float4*)&xp[(size_t)gm * D + k0 + (qb + r) * 4];
            }
        }

        // compute: 2 k-steps on current chunk
#pragma unroll
        for (int ks2 = 0; ks2 < 2; ks2++) {
            int kofs = ks2 * 8;               // half2 offset within chunk
            int wk = ck * 16 + kofs;          // half2 offset within W
            uint32_t a[4][4], b[4][2];
#pragma unroll
            for (int mi = 0; mi < 4; mi++) {
                int r = wm * 64 + mi * 16 + g;
                a[mi][0] = Xh[cur][r][kofs + c];
                a[mi][1] = Xh[cur][r + 8][kofs + c];
                a[mi][2] = Xh[cur][r][kofs + c + 4];
                a[mi][3] = Xh[cur][r + 8][kofs + c + 4];
            }
#pragma unroll
            for (int ni = 0; ni < 4; ni++) {
                int n = wn * 32 + ni * 8 + g;
                b[ni][0] = Wh[n][wk + c];
                b[ni][1] = Wh[n][wk + c + 4];
            }
#pragma unroll
            for (int mi = 0; mi < 4; mi++)
#pragma unroll
                for (int ni = 0; ni < 4; ni++)
                    mma_f16(acc[mi][ni], a[mi], b[ni]);
        }

        // store prefetched chunk into other buffer
        if (ck + 1 < NCHUNK) {
#pragma unroll
            for (int r = 0; r < 4; r++) {
                Xh[1 - cur][sm_][(qb + r) * 2]     = pack_h2(p[r].x, p[r].y);
                Xh[1 - cur][sm_][(qb + r) * 2 + 1] = pack_h2(p[r].z, p[r].w);
            }
        }
        __syncthreads();
    }

    // epilogue: convert to fp16, write half2 per fragment pair
#pragma unroll
    for (int ni = 0; ni < 4; ni++) {
        int cb = wn * 32 + ni * 8 + 2 * c;
#pragma unroll
        for (int mi = 0; mi < 4; mi++) {
            int r0 = m0 + wm * 64 + mi * 16 + g;
            int r1 = r0 + 8;
            if (r0 < N)
                *(__half2*)&h[(size_t)r0 * D + cb] =
                    __floats2half2_rn(acc[mi][ni][0], acc[mi][ni][1]);
            if (r1 < N)
                *(__half2*)&h[(size_t)r1 * D + cb] =
                    __floats2half2_rn(acc[mi][ni][2], acc[mi][ni][3]);
        }
    }
}

// ---------------------------------------------------------------------------
// Aggregation: out_s[i] = sum_j norm_ij * h_s[j]  + b_s   (fp32 accumulate)
// One warp per node. Lanes 0-15 handle sets {0,1}, lanes 16-31 sets {2,3}.
__global__ void k_agg(const float* __restrict__ b1, const float* __restrict__ b2,
                      float* __restrict__ out, int N) {
    int gt = blockIdx.x * blockDim.x + threadIdx.x;
    int i = gt >> 5;
    int lane = gt & 31;
    if (i >= N) return;

    int pair = lane >> 4;        // 0 -> sets 0,1 ; 1 -> sets 2,3
    int cp = lane & 15;          // uint4 column index (8 halves)
    int setA = pair * 2;         // 0 or 2  (bias b1)
    int setB = setA + 1;         // 1 or 3  (bias b2)

    const uint4* HA = (const uint4*)(g_h + (size_t)setA * N * D);
    const uint4* HB = (const uint4*)(g_h + (size_t)setB * N * D);

    float di = g_dis[i];
    float d2 = di * di;

    float accA[8], accB[8];
    {   // self-loop term
        uint4 ua = HA[(size_t)i * 16 + cp];
        uint4 ub = HB[(size_t)i * 16 + cp];
        const half2* pa = (const half2*)&ua;
        const half2* pb = (const half2*)&ub;
#pragma unroll
        for (int q = 0; q < 4; q++) {
            float2 fa = __half22float2(pa[q]);
            float2 fb = __half22float2(pb[q]);
            accA[2 * q] = fa.x * d2; accA[2 * q + 1] = fa.y * d2;
            accB[2 * q] = fb.x * d2; accB[2 * q + 1] = fb.y * d2;
        }
    }

    int beg = g_off[i];
    int end = beg + g_deg[i];
    for (int j = beg; j < end; j++) {
        int s = g_src[j];
        float w = di * g_dis[s];
        uint4 ua = HA[(size_t)s * 16 + cp];
        uint4 ub = HB[(size_t)s * 16 + cp];
        const half2* pa = (const half2*)&ua;
        const half2* pb = (const half2*)&ub;
#pragma unroll
        for (int q = 0; q < 4; q++) {
            float2 fa = __half22float2(pa[q]);
            float2 fb = __half22float2(pb[q]);
            accA[2 * q]     = fmaf(fa.x, w, accA[2 * q]);
            accA[2 * q + 1] = fmaf(fa.y, w, accA[2 * q + 1]);
            accB[2 * q]     = fmaf(fb.x, w, accB[2 * q]);
            accB[2 * q + 1] = fmaf(fb.y, w, accB[2 * q + 1]);
        }
    }

    // bias + write
    int col = cp * 8;
    float4 bA0 = *(const float4*)&b1[col];
    float4 bA1 = *(const float4*)&b1[col + 4];
    float4 bB0 = *(const float4*)&b2[col];
    float4 bB1 = *(const float4*)&b2[col + 4];

    float* oA = out + (size_t)setA * N * D + (size_t)i * D + col;
    float* oB = out + (size_t)setB * N * D + (size_t)i * D + col;
    *(float4*)oA       = make_float4(accA[0] + bA0.x, accA[1] + bA0.y,
                                     accA[2] + bA0.z, accA[3] + bA0.w);
    *(float4*)(oA + 4) = make_float4(accA[4] + bA1.x, accA[5] + bA1.y,
                                     accA[6] + bA1.z, accA[7] + bA1.w);
    *(float4*)oB       = make_float4(accB[0] + bB0.x, accB[1] + bB0.y,
                                     accB[2] + bB0.z, accB[3] + bB0.w);
    *(float4*)(oB + 4) = make_float4(accB[4] + bB1.x, accB[5] + bB1.y,
                                     accB[6] + bB1.z, accB[7] + bB1.w);
}

// ---------------------------------------------------------------------------
extern "C" void kernel_launch(void* const* d_in, const int* in_sizes, int n_in,
                              void* d_out, int out_size) {
    const float* x0 = (const float*)d_in[0];  // x_r1 (W1,b1)
    const float* x1 = (const float*)d_in[1];  // x_r2 (W2,b2)
    const float* x2 = (const float*)d_in[2];  // x_i1 (W1,b1)
    const float* x3 = (const float*)d_in[3];  // x_i2 (W2,b2)
    const void*  ei = d_in[4];                // edge_index: int64 OR int32
    const float* W1 = (const float*)d_in[5];
    const float* b1 = (const float*)d_in[6];
    const float* W2 = (const float*)d_in[7];
    const float* b2 = (const float*)d_in[8];
    float* out = (float*)d_out;

    int N = in_sizes[0] / D;
    int E = in_sizes[4] / 2;
    int nb_scan = (N + SCAN_B - 1) / SCAN_B;

    // dtype probe + zero + CSR build + normalization
    k_detect_zero<<<(N + 255) / 256, 256>>>(ei, E, N);
    k_count<<<(E + 255) / 256, 256>>>(ei, E, N);

    // GEMM first (independent of CSR): h = fp16(x @ W^T), no bias
    {
        dim3 grid((N + 127) / 128, 4);
        k_gemm<<<grid, 256>>>(x0, x1, x2, x3, W1, W2, N);
    }

    k_scan_block<<<nb_scan, SCAN_B>>>(N);
    k_scan_sums<<<1, 32>>>(nb_scan);
    k_finalize<<<(N + 255) / 256, 256>>>(N);
    k_fill<<<(E + 255) / 256, 256>>>(ei, E, N);

    // aggregate fp16 h with fp32 accumulation, add bias, write out
    {
        long long threads = (long long)N * 32;
        int blocks = (int)((threads + 255) / 256);
        k_agg<<<blocks, 256>>>(b1, b2, out, N);
    }
}

// round 12
// speedup vs baseline: 1.1406x; 1.0201x over previous
#include <cuda_runtime.h>
#include <cuda_fp16.h>
#include <cstdint>

#define MAX_N 50000
#define MAX_E 800000
#define D 128
#define SCAN_B 512
#define MAX_BLK 128   // >= ceil(MAX_N/SCAN_B)

// Scratch (device globals: allocation forbidden in kernel_launch)
__device__ int    g_mode;             // 1 = edge_index is int64, 0 = int32
__device__ int    g_deg[MAX_N];       // edge in-degree (excl self-loop)
__device__ int    g_off[MAX_N];       // CSR row offsets
__device__ int    g_cur[MAX_N];       // fill cursors
__device__ int    g_bsum[MAX_BLK];    // scan block sums
__device__ int    g_scan_ctr;         // last-block ticket (zero-init, self-reset)
__device__ float  g_dis[MAX_N];       // rsqrt(deg+1)
__device__ int    g_src[MAX_E];       // CSR column indices (source nodes)
__device__ __half g_h[4ull * MAX_N * D];  // h = x @ W^T in fp16, per set

// ---------------------------------------------------------------------------
// fused: zero degree array + dtype probe (thread 0 of block 0)
__global__ void k_detect_zero(const void* ei, int E, int N) {
    int i = blockIdx.x * blockDim.x + threadIdx.x;
    if (i < N) g_deg[i] = 0;
    if (i == 0) {
        const long long* p64 = (const long long*)ei;
        int n = E < 32 ? E : 32;
        int ok64 = 1;
        for (int k = 0; k < n; k++) {
            long long v = p64[k];
            if (v < 0 || v >= (long long)N) { ok64 = 0; break; }
        }
        g_mode = ok64;
    }
}

__device__ __forceinline__ int edge_at(const void* ei, long long idx, int mode) {
    if (mode) return (int)((const long long*)ei)[idx];
    return ((const int*)ei)[idx];
}

__global__ void k_count(const void* __restrict__ ei, int E, int N) {
    int e = blockIdx.x * blockDim.x + threadIdx.x;
    if (e >= E) return;
    int mode = g_mode;
    int d = edge_at(ei, (long long)E + e, mode);
    if (d >= 0 && d < N) atomicAdd(&g_deg[d], 1);
}

// per-block exclusive scan; last-arriving block scans the block sums in place
__global__ void k_scan_block(int N, int nb) {
    __shared__ int sm[SCAN_B];
    int i = blockIdx.x * SCAN_B + threadIdx.x;
    int v = (i < N) ? g_deg[i] : 0;
    sm[threadIdx.x] = v;
    __syncthreads();
#pragma unroll
    for (int o = 1; o < SCAN_B; o <<= 1) {
        int t = (threadIdx.x >= o) ? sm[threadIdx.x - o] : 0;
        __syncthreads();
        sm[threadIdx.x] += t;
        __syncthreads();
    }
    if (i < N) g_off[i] = sm[threadIdx.x] - v;   // exclusive (local)
    if (threadIdx.x == SCAN_B - 1) g_bsum[blockIdx.x] = sm[SCAN_B - 1];
    __syncthreads();
    if (threadIdx.x == 0) {
        __threadfence();                          // bsum visible before ticket
        int t = atomicAdd(&g_scan_ctr, 1);
        if (t == nb - 1) {
            g_scan_ctr = 0;                       // reset for next replay
            __threadfence();                      // acquire others' bsum
            int acc = 0;
            for (int b = 0; b < nb; b++) { int s = g_bsum[b]; g_bsum[b] = acc; acc += s; }
        }
    }
}

__global__ void k_finalize(int N) {
    int i = blockIdx.x * blockDim.x + threadIdx.x;
    if (i < N) {
        int o = g_off[i] + g_bsum[i / SCAN_B];
        g_off[i] = o;
        g_cur[i] = o;
        g_dis[i] = rsqrtf((float)(g_deg[i] + 1));
    }
}

__global__ void k_fill(const void* __restrict__ ei, int E, int N) {
    int e = blockIdx.x * blockDim.x + threadIdx.x;
    if (e >= E) return;
    int mode = g_mode;
    int s = edge_at(ei, e, mode);
    int d = edge_at(ei, (long long)E + e, mode);
    if (s >= 0 && s < N && d >= 0 && d < N) {
        int pos = atomicAdd(&g_cur[d], 1);
        if (pos >= 0 && pos < E) g_src[pos] = s;
    }
}

// ---------------------------------------------------------------------------
// GEMM (no bias): g_h[set] = fp16( x_set @ W^T )   (fp16 HMMA m16n8k16, f32 acc)
// Block 128(M)x128(N), 8 warps as 2(M)x4(N), warp 64x32.
// grid.y = weight pair p; block computes sets {p, p+2} sharing one staged W.
// x streamed in K=32 chunks, double-buffered. __launch_bounds__(256,2).
#define GP 68   // W pitch (half2 units): (4g+c)%32 distinct -> conflict-free
#define XP 20   // x chunk pitch (half2 units): (20g+c)%32 distinct -> conflict-free
#define NCHUNK 4  // 128 / 32

__device__ __forceinline__ uint32_t pack_h2(float lo, float hi) {
    __half2 h = __floats2half2_rn(lo, hi);
    return *(uint32_t*)&h;
}

__device__ __forceinline__ void mma_f16(float* d, const uint32_t* a, const uint32_t* b) {
    asm volatile(
        "mma.sync.aligned.m16n8k16.row.col.f32.f16.f16.f32 "
        "{%0,%1,%2,%3}, {%4,%5,%6,%7}, {%8,%9}, {%0,%1,%2,%3};"
        : "+f"(d[0]), "+f"(d[1]), "+f"(d[2]), "+f"(d[3])
        : "r"(a[0]), "r"(a[1]), "r"(a[2]), "r"(a[3]), "r"(b[0]), "r"(b[1]));
}

__global__ void __launch_bounds__(256, 2) k_gemm(
        const float* __restrict__ x0, const float* __restrict__ x1,
        const float* __restrict__ x2, const float* __restrict__ x3,
        const float* __restrict__ W1, const float* __restrict__ W2,
        int N) {
    __shared__ uint32_t Wh[128][GP];      // W[n][k] half2, full K (shared by 2 sets)
    __shared__ uint32_t Xh[2][128][XP];   // x chunk [m][k2], double buffer

    int p = blockIdx.y;                   // weight pair: 0 -> W1 (sets 0,2), 1 -> W2 (sets 1,3)
    const float* Wp = p ? W2 : W1;

    int tid = threadIdx.x;
    int m0 = blockIdx.x * 128;
    int warp = tid >> 5, lane = tid & 31;
    int wm = warp >> 2, wn = warp & 3;        // 2 x 4 warp grid
    int g = lane >> 2, c = lane & 3;

    // stage full W once: 128 rows x 32 float4
    for (int idx = tid; idx < 128 * 32; idx += 256) {
        int n = idx >> 5, q4 = idx & 31;
        float4 v = *(const float4*)&Wp[n * D + q4 * 4];
        Wh[n][q4 * 2]     = pack_h2(v.x, v.y);
        Wh[n][q4 * 2 + 1] = pack_h2(v.z, v.w);
    }

    int sm_ = tid >> 1;                 // staging row (2 threads per row)
    int qb = (tid & 1) * 4;             // first of 4 float4 slots (of 8)
    int gm = m0 + sm_;

    for (int ss = 0; ss < 2; ss++) {
        int set = p + ss * 2;
        const float* xp = (set == 0) ? x0 : (set == 1) ? x1 : (set == 2) ? x2 : x3;
        __half* h = g_h + (size_t)set * N * D;

        // stage x chunk 0 (K=32): 4 float4/thread
        {
            float4 q[4];
#pragma unroll
            for (int r = 0; r < 4; r++) {
                q[r] = make_float4(0.f, 0.f, 0.f, 0.f);
                if (gm < N) q[r] = *(const float4*)&xp[(size_t)gm * D + (qb + r) * 4];
            }
#pragma unroll
            for (int r = 0; r < 4; r++) {
                Xh[0][sm_][(qb + r) * 2]     = pack_h2(q[r].x, q[r].y);
                Xh[0][sm_][(qb + r) * 2 + 1] = pack_h2(q[r].z, q[r].w);
            }
        }
        __syncthreads();

        float acc[4][4][4];
#pragma unroll
        for (int mi = 0; mi < 4; mi++)
#pragma unroll
            for (int ni = 0; ni < 4; ni++)
#pragma unroll
                for (int r = 0; r < 4; r++) acc[mi][ni][r] = 0.0f;

        for (int ck = 0; ck < NCHUNK; ck++) {
            int cur = ck & 1;
            // prefetch next chunk (4 consecutive LDG.128)
            float4 q[4];
            if (ck + 1 < NCHUNK) {
                int k0 = (ck + 1) * 32;
#pragma unroll
                for (int r = 0; r < 4; r++) {
                    q[r] = make_float4(0.f, 0.f, 0.f, 0.f);
                    if (gm < N) q[r] = *(const float4*)&xp[(size_t)gm * D + k0 + (qb + r) * 4];
                }
            }

            // compute: 2 k-steps on current chunk
#pragma unroll
            for (int ks2 = 0; ks2 < 2; ks2++) {
                int kofs = ks2 * 8;               // half2 offset within chunk
                int wk = ck * 16 + kofs;          // half2 offset within W
                uint32_t a[4][4], b[4][2];
#pragma unroll
                for (int mi = 0; mi < 4; mi++) {
                    int r = wm * 64 + mi * 16 + g;
                    a[mi][0] = Xh[cur][r][kofs + c];
                    a[mi][1] = Xh[cur][r + 8][kofs + c];
                    a[mi][2] = Xh[cur][r][kofs + c + 4];
                    a[mi][3] = Xh[cur][r + 8][kofs + c + 4];
                }
#pragma unroll
                for (int ni = 0; ni < 4; ni++) {
                    int n = wn * 32 + ni * 8 + g;
                    b[ni][0] = Wh[n][wk + c];
                    b[ni][1] = Wh[n][wk + c + 4];
                }
#pragma unroll
                for (int mi = 0; mi < 4; mi++)
#pragma unroll
                    for (int ni = 0; ni < 4; ni++)
                        mma_f16(acc[mi][ni], a[mi], b[ni]);
            }

            // store prefetched chunk into other buffer
            if (ck + 1 < NCHUNK) {
#pragma unroll
                for (int r = 0; r < 4; r++) {
                    Xh[1 - cur][sm_][(qb + r) * 2]     = pack_h2(q[r].x, q[r].y);
                    Xh[1 - cur][sm_][(qb + r) * 2 + 1] = pack_h2(q[r].z, q[r].w);
                }
            }
            __syncthreads();
        }

        // epilogue: convert to fp16, write half2 per fragment pair
#pragma unroll
        for (int ni = 0; ni < 4; ni++) {
            int cb = wn * 32 + ni * 8 + 2 * c;
#pragma unroll
            for (int mi = 0; mi < 4; mi++) {
                int r0 = m0 + wm * 64 + mi * 16 + g;
                int r1 = r0 + 8;
                if (r0 < N)
                    *(__half2*)&h[(size_t)r0 * D + cb] =
                        __floats2half2_rn(acc[mi][ni][0], acc[mi][ni][1]);
                if (r1 < N)
                    *(__half2*)&h[(size_t)r1 * D + cb] =
                        __floats2half2_rn(acc[mi][ni][2], acc[mi][ni][3]);
            }
        }
        // no extra sync needed: next set's staging writes Xh[0], and the last
        // chunk-loop __syncthreads already ordered all Xh reads before it.
    }
}

// ---------------------------------------------------------------------------
// Aggregation: out_s[i] = sum_j norm_ij * h_s[j]  + b_s   (fp32 accumulate)
// One warp per node. Lanes 0-15 handle sets {0,1}, lanes 16-31 sets {2,3}.
__global__ void k_agg(const float* __restrict__ b1, const float* __restrict__ b2,
                      float* __restrict__ out, int N) {
    int gt = blockIdx.x * blockDim.x + threadIdx.x;
    int i = gt >> 5;
    int lane = gt & 31;
    if (i >= N) return;

    int pair = lane >> 4;        // 0 -> sets 0,1 ; 1 -> sets 2,3
    int cp = lane & 15;          // uint4 column index (8 halves)
    int setA = pair * 2;         // 0 or 2  (bias b1)
    int setB = setA + 1;         // 1 or 3  (bias b2)

    const uint4* HA = (const uint4*)(g_h + (size_t)setA * N * D);
    const uint4* HB = (const uint4*)(g_h + (size_t)setB * N * D);

    float di = g_dis[i];
    float d2 = di * di;

    float accA[8], accB[8];
    {   // self-loop term
        uint4 ua = HA[(size_t)i * 16 + cp];
        uint4 ub = HB[(size_t)i * 16 + cp];
        const half2* pa = (const half2*)&ua;
        const half2* pb = (const half2*)&ub;
#pragma unroll
        for (int q = 0; q < 4; q++) {
            float2 fa = __half22float2(pa[q]);
            float2 fb = __half22float2(pb[q]);
            accA[2 * q] = fa.x * d2; accA[2 * q + 1] = fa.y * d2;
            accB[2 * q] = fb.x * d2; accB[2 * q + 1] = fb.y * d2;
        }
    }

    int beg = g_off[i];
    int end = beg + g_deg[i];
    for (int j = beg; j < end; j++) {
        int s = g_src[j];
        float w = di * g_dis[s];
        uint4 ua = HA[(size_t)s * 16 + cp];
        uint4 ub = HB[(size_t)s * 16 + cp];
        const half2* pa = (const half2*)&ua;
        const half2* pb = (const half2*)&ub;
#pragma unroll
        for (int q = 0; q < 4; q++) {
            float2 fa = __half22float2(pa[q]);
            float2 fb = __half22float2(pb[q]);
            accA[2 * q]     = fmaf(fa.x, w, accA[2 * q]);
            accA[2 * q + 1] = fmaf(fa.y, w, accA[2 * q + 1]);
            accB[2 * q]     = fmaf(fb.x, w, accB[2 * q]);
            accB[2 * q + 1] = fmaf(fb.y, w, accB[2 * q + 1]);
        }
    }

    // bias + write
    int col = cp * 8;
    float4 bA0 = *(const float4*)&b1[col];
    float4 bA1 = *(const float4*)&b1[col + 4];
    float4 bB0 = *(const float4*)&b2[col];
    float4 bB1 = *(const float4*)&b2[col + 4];

    float* oA = out + (size_t)setA * N * D + (size_t)i * D + col;
    float* oB = out + (size_t)setB * N * D + (size_t)i * D + col;
    *(float4*)oA       = make_float4(accA[0] + bA0.x, accA[1] + bA0.y,
                                     accA[2] + bA0.z, accA[3] + bA0.w);
    *(float4*)(oA + 4) = make_float4(accA[4] + bA1.x, accA[5] + bA1.y,
                                     accA[6] + bA1.z, accA[7] + bA1.w);
    *(float4*)oB       = make_float4(accB[0] + bB0.x, accB[1] + bB0.y,
                                     accB[2] + bB0.z, accB[3] + bB0.w);
    *(float4*)(oB + 4) = make_float4(accB[4] + bB1.x, accB[5] + bB1.y,
                                     accB[6] + bB1.z, accB[7] + bB1.w);
}

// ---------------------------------------------------------------------------
extern "C" void kernel_launch(void* const* d_in, const int* in_sizes, int n_in,
                              void* d_out, int out_size) {
    const float* x0 = (const float*)d_in[0];  // x_r1 (W1,b1)
    const float* x1 = (const float*)d_in[1];  // x_r2 (W2,b2)
    const float* x2 = (const float*)d_in[2];  // x_i1 (W1,b1)
    const float* x3 = (const float*)d_in[3];  // x_i2 (W2,b2)
    const void*  ei = d_in[4];                // edge_index: int64 OR int32
    const float* W1 = (const float*)d_in[5];
    const float* b1 = (const float*)d_in[6];
    const float* W2 = (const float*)d_in[7];
    const float* b2 = (const float*)d_in[8];
    float* out = (float*)d_out;

    int N = in_sizes[0] / D;
    int E = in_sizes[4] / 2;
    int nb_scan = (N + SCAN_B - 1) / SCAN_B;

    // dtype probe + zero + CSR build + normalization
    k_detect_zero<<<(N + 255) / 256, 256>>>(ei, E, N);
    k_count<<<(E + 255) / 256, 256>>>(ei, E, N);

    // GEMM (independent of CSR): h = fp16(x @ W^T), no bias; 2 sets per block
    {
        dim3 grid((N + 127) / 128, 2);
        k_gemm<<<grid, 256>>>(x0, x1, x2, x3, W1, W2, N);
    }

    k_scan_block<<<nb_scan, SCAN_B>>>(N, nb_scan);
    k_finalize<<<(N + 255) / 256, 256>>>(N);
    k_fill<<<(E + 255) / 256, 256>>>(ei, E, N);

    // aggregate fp16 h with fp32 accumulation, add bias, write out
    {
        long long threads = (long long)N * 32;
        int blocks = (int)((threads + 255) / 256);
        k_agg<<<blocks, 256>>>(b1, b2, out, N);
    }
}